// round 5
// baseline (speedup 1.0000x reference)
#include <cuda_runtime.h>

#define E_EDGES 262144
#define DMODEL  128
#define NNODES  65536
#define PADF    132
#define LN_EPSF 1e-5f
#define SCALEF  0.17677669529663687f   // 1/sqrt(32)

// ---------------- scratch (device globals; no allocations allowed) ----------
__device__ float g_S[(size_t)NNODES * DMODEL];    // sum exp(s)*V per node
__device__ float g_den[(size_t)NNODES * 4];       // sum exp(s) per node/head
__device__ float g_Wt[4][DMODEL][DMODEL];         // tf32, transposed [w][n][k]
__device__ int   g_is64;

// ---------------- helpers ----------------------------------------------------
__device__ __forceinline__ float to_tf32(float x) {
    float r; asm("cvt.rna.tf32.f32 %0, %1;" : "=f"(r) : "f"(x)); return r;
}

__device__ __forceinline__ void mma_tf32(float c[4], const unsigned a[4],
                                         unsigned b0, unsigned b1) {
    asm volatile(
        "mma.sync.aligned.m16n8k8.row.col.f32.tf32.tf32.f32 "
        "{%0,%1,%2,%3}, {%4,%5,%6,%7}, {%8,%9}, {%0,%1,%2,%3};"
        : "+f"(c[0]), "+f"(c[1]), "+f"(c[2]), "+f"(c[3])
        : "r"(a[0]), "r"(a[1]), "r"(a[2]), "r"(a[3]), "r"(b0), "r"(b1));
}

__device__ __forceinline__ void red_add_v4(float* p, float x, float y, float z, float w) {
    asm volatile("red.global.add.v4.f32 [%0], {%1,%2,%3,%4};"
                 :: "l"(p), "f"(x), "f"(y), "f"(z), "f"(w) : "memory");
}
__device__ __forceinline__ void red_add_f(float* p, float v) {
    asm volatile("red.global.add.f32 [%0], %1;" :: "l"(p), "f"(v) : "memory");
}

__device__ __forceinline__ void cp_async16(float* smem_dst, const float* gsrc) {
    unsigned s = (unsigned)__cvta_generic_to_shared(smem_dst);
    asm volatile("cp.async.cg.shared.global [%0], [%1], 16;" :: "r"(s), "l"(gsrc));
}
__device__ __forceinline__ void cp_commit() {
    asm volatile("cp.async.commit_group;");
}
template <int N>
__device__ __forceinline__ void cp_wait() {
    asm volatile("cp.async.wait_group %0;" :: "n"(N));
}

__device__ __forceinline__ int node_of(const void* idx, int is64, size_t pos) {
    return is64 ? (int)((const long long*)idx)[pos] : ((const int*)idx)[pos];
}

// per-warp m32 x n32 tf32 GEMM tile: acc[mi][ni][q], warp grid 4m x 4n
__device__ __forceinline__ void gemm_tile32(const float* __restrict__ As,
                                            const float* __restrict__ Ws,
                                            float acc[2][4][4],
                                            int wm, int wn, int gr, int tg) {
    #pragma unroll
    for (int mi = 0; mi < 2; ++mi)
        #pragma unroll
        for (int ni = 0; ni < 4; ++ni)
            #pragma unroll
            for (int q = 0; q < 4; ++q) acc[mi][ni][q] = 0.f;
    #pragma unroll
    for (int kk = 0; kk < 16; ++kk) {
        int k0 = kk << 3;
        unsigned a[2][4];
        #pragma unroll
        for (int mi = 0; mi < 2; ++mi) {
            int r = wm * 32 + mi * 16 + gr;
            a[mi][0] = __float_as_uint(As[r * PADF + k0 + tg]);
            a[mi][1] = __float_as_uint(As[(r + 8) * PADF + k0 + tg]);
            a[mi][2] = __float_as_uint(As[r * PADF + k0 + tg + 4]);
            a[mi][3] = __float_as_uint(As[(r + 8) * PADF + k0 + tg + 4]);
        }
        #pragma unroll
        for (int ni = 0; ni < 4; ++ni) {
            int n = wn * 32 + ni * 8 + gr;
            unsigned b0 = __float_as_uint(Ws[n * PADF + k0 + tg]);
            unsigned b1 = __float_as_uint(Ws[n * PADF + k0 + tg + 4]);
            mma_tf32(acc[0][ni], a[0], b0, b1);
            mma_tf32(acc[1][ni], a[1], b0, b1);
        }
    }
}

// ---------------- kernel 0: edge_index dtype detection ----------------------
__global__ void detect_kernel(const int* __restrict__ idx) {
    if (threadIdx.x == 0) {
        int nz = 0;
        #pragma unroll 1
        for (int i = 0; i < 64; ++i) nz |= idx[2 * i + 1];
        g_is64 = (nz == 0) ? 1 : 0;
    }
}

// ---------------- kernel 1: zero init ----------------------------------------
__global__ void init_kernel() {
    size_t i = (size_t)blockIdx.x * blockDim.x + threadIdx.x;
    if (i < (size_t)NNODES * DMODEL / 4)
        ((float4*)g_S)[i] = make_float4(0.f, 0.f, 0.f, 0.f);
    if (i < (size_t)NNODES)
        ((float4*)g_den)[i] = make_float4(0.f, 0.f, 0.f, 0.f);
}

// ---------------- kernel 2: weight prep (transpose + tf32, once) -------------
__global__ void prep_kernel(const float* __restrict__ Wq, const float* __restrict__ Wk,
                            const float* __restrict__ Wv, const float* __restrict__ Wo) {
    __shared__ float t[32][33];
    const float* W[4] = {Wq, Wk, Wv, Wo};
    int w = blockIdx.z, k0 = blockIdx.x * 32, n0 = blockIdx.y * 32;
    int tx = threadIdx.x, ty = threadIdx.y;      // 32 x 8
    const float* src = W[w];
    #pragma unroll
    for (int j = 0; j < 32; j += 8)
        t[ty + j][tx] = to_tf32(src[(k0 + ty + j) * DMODEL + n0 + tx]);
    __syncthreads();
    #pragma unroll
    for (int j = 0; j < 32; j += 8)
        g_Wt[w][n0 + ty + j][k0 + tx] = t[tx][ty + j];
}

// ---------------- kernel 3: fused QKV + scores + scatter ---------------------
// 512 threads, warp grid 4m x 4n. Each n-warp owns exactly one head (32 cols).
__global__ __launch_bounds__(512, 1)
void fused_kernel(const float* __restrict__ X, const void* __restrict__ idx,
                  const float* __restrict__ bq, const float* __restrict__ bk,
                  const float* __restrict__ bv) {
    extern __shared__ float sm[];
    float* As  = sm;                       // [128][PADF] X tile
    float* Ws0 = sm + 128 * PADF;          // weight buffer 0
    float* Ws1 = sm + 2 * 128 * PADF;      // weight buffer 1
    float* sb  = sm + 3 * 128 * PADF;      // bq(128) bk(128) bv(128)
    int*  sidx = (int*)(sb + 384);         // src[128], dst[128]

    int tid = threadIdx.x, lane = tid & 31, warp = tid >> 5;
    int wm = warp & 3, wn = warp >> 2, gr = lane >> 2, tg = lane & 3;
    size_t e0 = (size_t)blockIdx.x * 128;
    int is64 = g_is64;

    // G0: X tile + Wq
    for (int i = tid; i < 4096; i += 512) {
        int r = i >> 5, c = (i & 31) << 2;
        cp_async16(As + r * PADF + c, X + (e0 + r) * DMODEL + c);
    }
    for (int i = tid; i < 4096; i += 512) {
        int n = i >> 5, c = (i & 31) << 2;
        cp_async16(Ws0 + n * PADF + c, &g_Wt[0][n][c]);
    }
    cp_commit();
    // G1: Wk
    for (int i = tid; i < 4096; i += 512) {
        int n = i >> 5, c = (i & 31) << 2;
        cp_async16(Ws1 + n * PADF + c, &g_Wt[1][n][c]);
    }
    cp_commit();

    // indices + biases while copies fly
    if (tid < 128)      sidx[tid] = node_of(idx, is64, e0 + tid);
    else if (tid < 256) sidx[tid] = node_of(idx, is64, (size_t)E_EDGES + e0 + (tid - 128));
    if (tid < 384)
        sb[tid] = (tid < 128) ? bq[tid] : (tid < 256 ? bk[tid - 128] : bv[tid - 256]);

    cp_wait<1>();      // As + Wq landed
    __syncthreads();

    float Qa[2][4][4];
    gemm_tile32(As, Ws0, Qa, wm, wn, gr, tg);     // Q
    __syncthreads();                               // done reading Ws0

    // G2: Wv into Ws0
    for (int i = tid; i < 4096; i += 512) {
        int n = i >> 5, c = (i & 31) << 2;
        cp_async16(Ws0 + n * PADF + c, &g_Wt[2][n][c]);
    }
    cp_commit();
    cp_wait<1>();      // Wk landed
    __syncthreads();

    float acc[2][4][4];
    gemm_tile32(As, Ws1, acc, wm, wn, gr, tg);    // K

    // scores for head `wn`: register dot + quad shuffle, then exp
    float ev[4];                                   // [mi*2 + sr]
    #pragma unroll
    for (int mi = 0; mi < 2; ++mi) {
        float s0 = 0.f, s1 = 0.f;
        #pragma unroll
        for (int ni = 0; ni < 4; ++ni) {
            int col = wn * 32 + ni * 8 + tg * 2;
            float bq0 = sb[col], bq1 = sb[col + 1];
            float bk0 = sb[128 + col], bk1 = sb[128 + col + 1];
            s0 += (Qa[mi][ni][0] + bq0) * (acc[mi][ni][0] + bk0)
                + (Qa[mi][ni][1] + bq1) * (acc[mi][ni][1] + bk1);
            s1 += (Qa[mi][ni][2] + bq0) * (acc[mi][ni][2] + bk0)
                + (Qa[mi][ni][3] + bq1) * (acc[mi][ni][3] + bk1);
        }
        s0 += __shfl_xor_sync(0xffffffffu, s0, 1);
        s0 += __shfl_xor_sync(0xffffffffu, s0, 2);
        s1 += __shfl_xor_sync(0xffffffffu, s1, 1);
        s1 += __shfl_xor_sync(0xffffffffu, s1, 2);
        ev[mi * 2]     = __expf(s0 * SCALEF);
        ev[mi * 2 + 1] = __expf(s1 * SCALEF);
    }

    cp_wait<0>();      // Wv landed
    __syncthreads();

    gemm_tile32(As, Ws0, acc, wm, wn, gr, tg);    // V

    // scatter from registers
    #pragma unroll
    for (int mi = 0; mi < 2; ++mi) {
        #pragma unroll
        for (int sr = 0; sr < 2; ++sr) {
            int row = wm * 32 + mi * 16 + sr * 8 + gr;
            int src = sidx[row], dst = sidx[128 + row];
            float* ps = g_S + (size_t)src * DMODEL;
            float* pd = g_S + (size_t)dst * DMODEL;
            float w = ev[mi * 2 + sr];
            if (tg == 0) {
                red_add_f(&g_den[(size_t)src * 4 + wn], w);
                red_add_f(&g_den[(size_t)dst * 4 + wn], w);
            }
            #pragma unroll
            for (int ni = 0; ni < 4; ++ni) {
                int col = wn * 32 + ni * 8 + tg * 2;
                float v0 = (acc[mi][ni][sr * 2]     + sb[256 + col])     * w;
                float v1 = (acc[mi][ni][sr * 2 + 1] + sb[256 + col + 1]) * w;
                float p0 = __shfl_xor_sync(0xffffffffu, v0, 1);
                float p1 = __shfl_xor_sync(0xffffffffu, v1, 1);
                if (!(tg & 1)) {
                    red_add_v4(ps + col, v0, v1, p0, p1);
                    red_add_v4(pd + col, v0, v1, p0, p1);
                }
            }
        }
    }
}

// ---------------- kernel 4: gather + Wo GEMM + residual + LayerNorm ----------
__global__ __launch_bounds__(512, 1)
void out_kernel(const void* __restrict__ idx, const float* __restrict__ X,
                const float* __restrict__ bo, const float* __restrict__ gamma,
                const float* __restrict__ beta, float* __restrict__ out) {
    extern __shared__ float sm[];
    float* Ms  = sm;                       // msg tile
    float* Ws  = sm + 128 * PADF;          // Wo^T tf32
    float* Xs  = sm + 2 * 128 * PADF;      // residual X tile
    float* sb  = sm + 3 * 128 * PADF;      // bo(128) gamma(128) beta(128)
    float* red = sb + 384;                 // [128][8] per-row {sum,sq} x 4 n-warps

    int tid = threadIdx.x, lane = tid & 31, warp = tid >> 5;
    int wm = warp & 3, wn = warp >> 2, gr = lane >> 2, tg = lane & 3;
    size_t e0 = (size_t)blockIdx.x * 128;
    int is64 = g_is64;

    for (int i = tid; i < 4096; i += 512) {
        int r = i >> 5, c = (i & 31) << 2;
        cp_async16(Xs + r * PADF + c, X + (e0 + r) * DMODEL + c);
    }
    for (int i = tid; i < 4096; i += 512) {
        int n = i >> 5, c = (i & 31) << 2;
        cp_async16(Ws + n * PADF + c, &g_Wt[3][n][c]);
    }
    cp_commit();

    if (tid < 384)
        sb[tid] = (tid < 128) ? bo[tid] : (tid < 256 ? gamma[tid - 128] : beta[tid - 256]);

    {   // build msg tile: 4 threads per row, one head (32 cols) each
        int r = tid >> 2, hf = tid & 3;
        size_t e = e0 + r;
        int src = node_of(idx, is64, e);
        int dst = node_of(idx, is64, (size_t)E_EDGES + e);
        float fs = 0.5f / g_den[(size_t)src * 4 + hf];
        float fd = 0.5f / g_den[(size_t)dst * 4 + hf];
        const float* Ssrc = g_S + (size_t)src * DMODEL + hf * 32;
        const float* Sdst = g_S + (size_t)dst * DMODEL + hf * 32;
        #pragma unroll
        for (int j = 0; j < 8; ++j) {
            int c = j * 4;
            float4 a = *(const float4*)(Ssrc + c);
            float4 b = *(const float4*)(Sdst + c);
            int cc = hf * 32 + c;
            Ms[r * PADF + cc + 0] = a.x * fs + b.x * fd;
            Ms[r * PADF + cc + 1] = a.y * fs + b.y * fd;
            Ms[r * PADF + cc + 2] = a.z * fs + b.z * fd;
            Ms[r * PADF + cc + 3] = a.w * fs + b.w * fd;
        }
    }
    cp_wait<0>();
    __syncthreads();

    float acc[2][4][4];
    gemm_tile32(Ms, Ws, acc, wm, wn, gr, tg);

    // epilogue: + bo + residual, LN partials per (mi, sr)
    float rs[2][2], rq[2][2];
    #pragma unroll
    for (int mi = 0; mi < 2; ++mi)
        #pragma unroll
        for (int sr = 0; sr < 2; ++sr) { rs[mi][sr] = 0.f; rq[mi][sr] = 0.f; }

    #pragma unroll
    for (int mi = 0; mi < 2; ++mi) {
        #pragma unroll
        for (int ni = 0; ni < 4; ++ni) {
            int col = wn * 32 + ni * 8 + tg * 2;
            float b0v = sb[col], b1v = sb[col + 1];
            #pragma unroll
            for (int sr = 0; sr < 2; ++sr) {
                int row = wm * 32 + mi * 16 + sr * 8 + gr;
                float x0 = Xs[row * PADF + col], x1 = Xs[row * PADF + col + 1];
                float o0 = acc[mi][ni][sr * 2]     + b0v + x0;
                float o1 = acc[mi][ni][sr * 2 + 1] + b1v + x1;
                acc[mi][ni][sr * 2]     = o0;
                acc[mi][ni][sr * 2 + 1] = o1;
                rs[mi][sr] += o0 + o1;
                rq[mi][sr] += o0 * o0 + o1 * o1;
            }
        }
    }
    #pragma unroll
    for (int mi = 0; mi < 2; ++mi)
        #pragma unroll
        for (int sr = 0; sr < 2; ++sr) {
            float s = rs[mi][sr], q = rq[mi][sr];
            s += __shfl_xor_sync(0xffffffffu, s, 1);
            s += __shfl_xor_sync(0xffffffffu, s, 2);
            q += __shfl_xor_sync(0xffffffffu, q, 1);
            q += __shfl_xor_sync(0xffffffffu, q, 2);
            if (tg == 0) {
                int row = wm * 32 + mi * 16 + sr * 8 + gr;
                red[row * 8 + wn * 2]     = s;
                red[row * 8 + wn * 2 + 1] = q;
            }
        }
    __syncthreads();

    #pragma unroll
    for (int mi = 0; mi < 2; ++mi) {
        #pragma unroll
        for (int sr = 0; sr < 2; ++sr) {
            int row = wm * 32 + mi * 16 + sr * 8 + gr;
            float s = red[row * 8] + red[row * 8 + 2] + red[row * 8 + 4] + red[row * 8 + 6];
            float q = red[row * 8 + 1] + red[row * 8 + 3] + red[row * 8 + 5] + red[row * 8 + 7];
            float mu = s * (1.0f / 128.0f);
            float var = q * (1.0f / 128.0f) - mu * mu;
            float rstd = rsqrtf(var + LN_EPSF);
            float* orow = out + (e0 + row) * DMODEL;
            #pragma unroll
            for (int ni = 0; ni < 4; ++ni) {
                int col = wn * 32 + ni * 8 + tg * 2;
                float g0 = sb[128 + col], g1 = sb[128 + col + 1];
                float b0v = sb[256 + col], b1v = sb[256 + col + 1];
                float v0 = (acc[mi][ni][sr * 2]     - mu) * rstd * g0 + b0v;
                float v1 = (acc[mi][ni][sr * 2 + 1] - mu) * rstd * g1 + b1v;
                float p0 = __shfl_xor_sync(0xffffffffu, v0, 1);
                float p1 = __shfl_xor_sync(0xffffffffu, v1, 1);
                if (!(tg & 1)) *(float4*)(orow + col) = make_float4(v0, v1, p0, p1);
            }
        }
    }
}

// ---------------- host -------------------------------------------------------
#define SMEM_FUSED ((3 * 128 * PADF + 384) * 4 + 256 * 4)
#define SMEM_OUT   ((3 * 128 * PADF + 384 + 1024) * 4)

extern "C" void kernel_launch(void* const* d_in, const int* in_sizes, int n_in,
                              void* d_out, int out_size) {
    const float* X   = (const float*)d_in[0];
    const void*  idx = d_in[1];
    int base = 2;
    if (n_in >= 13 && in_sizes[2] == 1) base = 3;
    const float* Wq    = (const float*)d_in[base + 0];
    const float* bq    = (const float*)d_in[base + 1];
    const float* Wk    = (const float*)d_in[base + 2];
    const float* bk    = (const float*)d_in[base + 3];
    const float* Wv    = (const float*)d_in[base + 4];
    const float* bv    = (const float*)d_in[base + 5];
    const float* Wo    = (const float*)d_in[base + 6];
    const float* bo    = (const float*)d_in[base + 7];
    const float* gamma = (const float*)d_in[base + 8];
    const float* beta  = (const float*)d_in[base + 9];
    float* out = (float*)d_out;

    cudaFuncSetAttribute(fused_kernel, cudaFuncAttributeMaxDynamicSharedMemorySize, SMEM_FUSED);
    cudaFuncSetAttribute(out_kernel,   cudaFuncAttributeMaxDynamicSharedMemorySize, SMEM_OUT);

    detect_kernel<<<1, 32>>>((const int*)idx);
    init_kernel<<<8192, 256>>>();
    prep_kernel<<<dim3(4, 4, 4), dim3(32, 8)>>>(Wq, Wk, Wv, Wo);
    fused_kernel<<<E_EDGES / 128, 512, SMEM_FUSED>>>(X, idx, bq, bk, bv);
    out_kernel<<<E_EDGES / 128, 512, SMEM_OUT>>>(idx, X, bo, gamma, beta, out);
}

// round 6
// speedup vs baseline: 1.4624x; 1.4624x over previous
#include <cuda_runtime.h>

#define E_EDGES 262144
#define DMODEL  128
#define NNODES  65536
#define PADF    132
#define LN_EPSF 1e-5f
#define SCALEF  0.17677669529663687f   // 1/sqrt(32)

// ---------------- scratch (device globals; no allocations allowed) ----------
__device__ float g_S[(size_t)NNODES * DMODEL];    // sum exp(s)*V per node
__device__ float g_den[(size_t)NNODES * 4];       // sum exp(s) per node/head
__device__ float g_T[(size_t)NNODES * DMODEL];    // (0.5*S/den) @ Wo per node
__device__ float g_Wt[4][DMODEL][DMODEL];         // tf32, transposed [w][n][k]
__device__ int   g_is64;

// ---------------- helpers ----------------------------------------------------
__device__ __forceinline__ float to_tf32(float x) {
    float r; asm("cvt.rna.tf32.f32 %0, %1;" : "=f"(r) : "f"(x)); return r;
}

__device__ __forceinline__ void mma_tf32(float c[4], const unsigned a[4],
                                         unsigned b0, unsigned b1) {
    asm volatile(
        "mma.sync.aligned.m16n8k8.row.col.f32.tf32.tf32.f32 "
        "{%0,%1,%2,%3}, {%4,%5,%6,%7}, {%8,%9}, {%0,%1,%2,%3};"
        : "+f"(c[0]), "+f"(c[1]), "+f"(c[2]), "+f"(c[3])
        : "r"(a[0]), "r"(a[1]), "r"(a[2]), "r"(a[3]), "r"(b0), "r"(b1));
}

__device__ __forceinline__ void red_add_v4(float* p, float x, float y, float z, float w) {
    asm volatile("red.global.add.v4.f32 [%0], {%1,%2,%3,%4};"
                 :: "l"(p), "f"(x), "f"(y), "f"(z), "f"(w) : "memory");
}
__device__ __forceinline__ void red_add_v2(float* p, float x, float y) {
    asm volatile("red.global.add.v2.f32 [%0], {%1,%2};"
                 :: "l"(p), "f"(x), "f"(y) : "memory");
}

__device__ __forceinline__ void cp_async16(float* smem_dst, const float* gsrc) {
    unsigned s = (unsigned)__cvta_generic_to_shared(smem_dst);
    asm volatile("cp.async.cg.shared.global [%0], [%1], 16;" :: "r"(s), "l"(gsrc));
}
__device__ __forceinline__ void cp_commit() {
    asm volatile("cp.async.commit_group;");
}
template <int N>
__device__ __forceinline__ void cp_wait() {
    asm volatile("cp.async.wait_group %0;" :: "n"(N));
}

__device__ __forceinline__ int node_of(const void* idx, int is64, size_t pos) {
    return is64 ? (int)((const long long*)idx)[pos] : ((const int*)idx)[pos];
}

// per-warp m32 x n64 tf32 GEMM tile: acc[mi][ni][q], warp grid 4m x 2n (256 thr)
__device__ __forceinline__ void gemm_tile64(const float* __restrict__ As,
                                            const float* __restrict__ Ws,
                                            float acc[2][8][4],
                                            int wm, int wn, int gr, int tg) {
    #pragma unroll
    for (int mi = 0; mi < 2; ++mi)
        #pragma unroll
        for (int ni = 0; ni < 8; ++ni)
            #pragma unroll
            for (int q = 0; q < 4; ++q) acc[mi][ni][q] = 0.f;
    #pragma unroll
    for (int kk = 0; kk < 16; ++kk) {
        int k0 = kk << 3;
        unsigned a[2][4];
        #pragma unroll
        for (int mi = 0; mi < 2; ++mi) {
            int r = wm * 32 + mi * 16 + gr;
            a[mi][0] = __float_as_uint(As[r * PADF + k0 + tg]);
            a[mi][1] = __float_as_uint(As[(r + 8) * PADF + k0 + tg]);
            a[mi][2] = __float_as_uint(As[r * PADF + k0 + tg + 4]);
            a[mi][3] = __float_as_uint(As[(r + 8) * PADF + k0 + tg + 4]);
        }
        #pragma unroll
        for (int ni = 0; ni < 8; ++ni) {
            int n = wn * 64 + ni * 8 + gr;
            unsigned b0 = __float_as_uint(Ws[n * PADF + k0 + tg]);
            unsigned b1 = __float_as_uint(Ws[n * PADF + k0 + tg + 4]);
            mma_tf32(acc[0][ni], a[0], b0, b1);
            mma_tf32(acc[1][ni], a[1], b0, b1);
        }
    }
}

// ---------------- kernel 0: edge_index dtype detection ----------------------
__global__ void detect_kernel(const int* __restrict__ idx) {
    if (threadIdx.x == 0) {
        int nz = 0;
        #pragma unroll 1
        for (int i = 0; i < 64; ++i) nz |= idx[2 * i + 1];
        g_is64 = (nz == 0) ? 1 : 0;
    }
}

// ---------------- kernel 1: zero init ----------------------------------------
__global__ void init_kernel() {
    size_t i = (size_t)blockIdx.x * blockDim.x + threadIdx.x;
    if (i < (size_t)NNODES * DMODEL / 4)
        ((float4*)g_S)[i] = make_float4(0.f, 0.f, 0.f, 0.f);
    if (i < (size_t)NNODES)
        ((float4*)g_den)[i] = make_float4(0.f, 0.f, 0.f, 0.f);
}

// ---------------- kernel 2: weight prep (transpose + tf32, once) -------------
__global__ void prep_kernel(const float* __restrict__ Wq, const float* __restrict__ Wk,
                            const float* __restrict__ Wv, const float* __restrict__ Wo) {
    __shared__ float t[32][33];
    const float* W[4] = {Wq, Wk, Wv, Wo};
    int w = blockIdx.z, k0 = blockIdx.x * 32, n0 = blockIdx.y * 32;
    int tx = threadIdx.x, ty = threadIdx.y;      // 32 x 8
    const float* src = W[w];
    #pragma unroll
    for (int j = 0; j < 32; j += 8)
        t[ty + j][tx] = to_tf32(src[(k0 + ty + j) * DMODEL + n0 + tx]);
    __syncthreads();
    #pragma unroll
    for (int j = 0; j < 32; j += 8)
        g_Wt[w][n0 + ty + j][k0 + tx] = t[tx][ty + j];
}

// ---------------- kernel 3: fused QKV + scores + scatter (R4-proven shape) ---
__global__ __launch_bounds__(256, 1)
void fused_kernel(const float* __restrict__ X, const void* __restrict__ idx,
                  const float* __restrict__ bq, const float* __restrict__ bk,
                  const float* __restrict__ bv) {
    extern __shared__ float sm[];
    float* As  = sm;                       // [128][PADF] X tile (raw fp32 -> tf32 trunc)
    float* Ws0 = sm + 128 * PADF;          // weight buffer 0
    float* Ws1 = sm + 2 * 128 * PADF;      // weight buffer 1
    float* sb  = sm + 3 * 128 * PADF;      // bq(128) bk(128) bv(128)
    int*  sidx = (int*)(sb + 384);         // src[128], dst[128]

    int tid = threadIdx.x, lane = tid & 31, warp = tid >> 5;
    int wm = warp & 3, wn = warp >> 2, gr = lane >> 2, tg = lane & 3;
    size_t e0 = (size_t)blockIdx.x * 128;
    int is64 = g_is64;

    // G0: X tile + Wq
    for (int i = tid; i < 4096; i += 256) {
        int r = i >> 5, c = (i & 31) << 2;
        cp_async16(As + r * PADF + c, X + (e0 + r) * DMODEL + c);
    }
    for (int i = tid; i < 4096; i += 256) {
        int n = i >> 5, c = (i & 31) << 2;
        cp_async16(Ws0 + n * PADF + c, &g_Wt[0][n][c]);
    }
    cp_commit();
    // G1: Wk
    for (int i = tid; i < 4096; i += 256) {
        int n = i >> 5, c = (i & 31) << 2;
        cp_async16(Ws1 + n * PADF + c, &g_Wt[1][n][c]);
    }
    cp_commit();

    // indices + biases while copies fly
    if (tid < 128) sidx[tid] = node_of(idx, is64, e0 + tid);
    else           sidx[tid] = node_of(idx, is64, (size_t)E_EDGES + e0 + (tid - 128));
    for (int i = tid; i < 384; i += 256)
        sb[i] = (i < 128) ? bq[i] : (i < 256 ? bk[i - 128] : bv[i - 256]);

    cp_wait<1>();      // As + Wq landed
    __syncthreads();

    float Qa[2][8][4];
    gemm_tile64(As, Ws0, Qa, wm, wn, gr, tg);    // Q
    __syncthreads();                              // done reading Ws0

    // G2: Wv into Ws0
    for (int i = tid; i < 4096; i += 256) {
        int n = i >> 5, c = (i & 31) << 2;
        cp_async16(Ws0 + n * PADF + c, &g_Wt[2][n][c]);
    }
    cp_commit();
    cp_wait<1>();      // Wk landed
    __syncthreads();

    float acc[2][8][4];
    gemm_tile64(As, Ws1, acc, wm, wn, gr, tg);   // K

    // scores: register-local dot (Q+bq).(K+bk), quad-shuffle reduce, exp
    float ev[8];                                  // [(mi<<2)|(sr<<1)|hl]
    #pragma unroll
    for (int mi = 0; mi < 2; ++mi) {
        #pragma unroll
        for (int hl = 0; hl < 2; ++hl) {
            float s0 = 0.f, s1 = 0.f;
            #pragma unroll
            for (int j = 0; j < 4; ++j) {
                int ni = hl * 4 + j;
                int col = wn * 64 + ni * 8 + tg * 2;
                float bq0 = sb[col], bq1 = sb[col + 1];
                float bk0 = sb[128 + col], bk1 = sb[128 + col + 1];
                s0 += (Qa[mi][ni][0] + bq0) * (acc[mi][ni][0] + bk0)
                    + (Qa[mi][ni][1] + bq1) * (acc[mi][ni][1] + bk1);
                s1 += (Qa[mi][ni][2] + bq0) * (acc[mi][ni][2] + bk0)
                    + (Qa[mi][ni][3] + bq1) * (acc[mi][ni][3] + bk1);
            }
            s0 += __shfl_xor_sync(0xffffffffu, s0, 1);
            s0 += __shfl_xor_sync(0xffffffffu, s0, 2);
            s1 += __shfl_xor_sync(0xffffffffu, s1, 1);
            s1 += __shfl_xor_sync(0xffffffffu, s1, 2);
            ev[(mi << 2) | (0 << 1) | hl] = __expf(s0 * SCALEF);
            ev[(mi << 2) | (1 << 1) | hl] = __expf(s1 * SCALEF);
        }
    }

    cp_wait<0>();      // Wv landed
    __syncthreads();

    gemm_tile64(As, Ws0, acc, wm, wn, gr, tg);   // V

    // scatter from registers: weighted V to src & dst, den per head
    #pragma unroll
    for (int mi = 0; mi < 2; ++mi) {
        #pragma unroll
        for (int sr = 0; sr < 2; ++sr) {
            int row = wm * 32 + mi * 16 + sr * 8 + gr;
            int src = sidx[row], dst = sidx[128 + row];
            float* ps = g_S + (size_t)src * DMODEL;
            float* pd = g_S + (size_t)dst * DMODEL;
            if (tg == 0) {
                float e0h = ev[(mi << 2) | (sr << 1)];
                float e1h = ev[(mi << 2) | (sr << 1) | 1];
                red_add_v2(&g_den[(size_t)src * 4 + wn * 2], e0h, e1h);
                red_add_v2(&g_den[(size_t)dst * 4 + wn * 2], e0h, e1h);
            }
            #pragma unroll
            for (int ni = 0; ni < 8; ++ni) {
                int col = wn * 64 + ni * 8 + tg * 2;
                float w = ev[(mi << 2) | (sr << 1) | (ni >> 2)];
                float v0 = (acc[mi][ni][sr * 2]     + sb[256 + col])     * w;
                float v1 = (acc[mi][ni][sr * 2 + 1] + sb[256 + col + 1]) * w;
                float p0 = __shfl_xor_sync(0xffffffffu, v0, 1);
                float p1 = __shfl_xor_sync(0xffffffffu, v1, 1);
                if (!(tg & 1)) {
                    red_add_v4(ps + col, v0, v1, p0, p1);
                    red_add_v4(pd + col, v0, v1, p0, p1);
                }
            }
        }
    }
}

// ---------------- kernel 4: per-NODE Wo GEMM: T = (0.5*S/den) @ Wo -----------
// 65536 rows instead of 262144 (linearity of Wo) -> 4x less GEMM work.
__global__ __launch_bounds__(256, 1)
void nodeT_kernel() {
    extern __shared__ float sm[];
    float* Ms = sm;                       // node msg tile
    float* Ws = sm + 128 * PADF;          // Wo^T tf32

    int tid = threadIdx.x, lane = tid & 31, warp = tid >> 5;
    int wm = warp & 3, wn = warp >> 2, gr = lane >> 2, tg = lane & 3;
    size_t n0 = (size_t)blockIdx.x * 128;

    for (int i = tid; i < 4096; i += 256) {
        int n = i >> 5, c = (i & 31) << 2;
        cp_async16(Ws + n * PADF + c, &g_Wt[3][n][c]);
    }
    cp_commit();

    {   // build tile: 2 threads per node row, 64 cols each
        int r = tid >> 1, hf = tid & 1;
        size_t node = n0 + r;
        float d0 = g_den[node * 4 + hf * 2], d1 = g_den[node * 4 + hf * 2 + 1];
        float f0 = (d0 > 0.f) ? 0.5f / d0 : 0.f;
        float f1 = (d1 > 0.f) ? 0.5f / d1 : 0.f;
        const float* Sp = g_S + node * DMODEL + hf * 64;
        #pragma unroll
        for (int j = 0; j < 16; ++j) {
            int c = j * 4;
            float f = (c < 32) ? f0 : f1;
            float4 a = *(const float4*)(Sp + c);
            int cc = hf * 64 + c;
            Ms[r * PADF + cc + 0] = a.x * f;
            Ms[r * PADF + cc + 1] = a.y * f;
            Ms[r * PADF + cc + 2] = a.z * f;
            Ms[r * PADF + cc + 3] = a.w * f;
        }
    }
    cp_wait<0>();
    __syncthreads();

    float acc[2][8][4];
    gemm_tile64(Ms, Ws, acc, wm, wn, gr, tg);

    #pragma unroll
    for (int mi = 0; mi < 2; ++mi) {
        int r0 = wm * 32 + mi * 16 + gr;
        #pragma unroll
        for (int ni = 0; ni < 8; ++ni) {
            int col = wn * 64 + ni * 8 + tg * 2;
            *(float2*)(g_T + (n0 + r0) * DMODEL + col)       = make_float2(acc[mi][ni][0], acc[mi][ni][1]);
            *(float2*)(g_T + (n0 + r0 + 8) * DMODEL + col)   = make_float2(acc[mi][ni][2], acc[mi][ni][3]);
        }
    }
}

// ---------------- kernel 5: edge epilogue: LN(T[src]+T[dst]+bo+X) ------------
// one warp per edge; T (32MB) is L2-resident.
__global__ __launch_bounds__(256)
void epi_kernel(const void* __restrict__ idx, const float* __restrict__ X,
                const float* __restrict__ bo, const float* __restrict__ gamma,
                const float* __restrict__ beta, float* __restrict__ out) {
    int tid = threadIdx.x, lane = tid & 31;
    size_t e = (size_t)blockIdx.x * 8 + (tid >> 5);
    int is64 = g_is64;

    int src = node_of(idx, is64, e);
    int dst = node_of(idx, is64, (size_t)E_EDGES + e);

    int c = lane * 4;
    float4 ts = *(const float4*)(g_T + (size_t)src * DMODEL + c);
    float4 td = *(const float4*)(g_T + (size_t)dst * DMODEL + c);
    float4 x4 = *(const float4*)(X + e * DMODEL + c);
    float4 b4 = *(const float4*)(bo + c);

    float4 v;
    v.x = ts.x + td.x + b4.x + x4.x;
    v.y = ts.y + td.y + b4.y + x4.y;
    v.z = ts.z + td.z + b4.z + x4.z;
    v.w = ts.w + td.w + b4.w + x4.w;

    float s = v.x + v.y + v.z + v.w;
    float q = v.x * v.x + v.y * v.y + v.z * v.z + v.w * v.w;
    #pragma unroll
    for (int o = 16; o > 0; o >>= 1) {
        s += __shfl_xor_sync(0xffffffffu, s, o);
        q += __shfl_xor_sync(0xffffffffu, q, o);
    }
    float mu = s * (1.0f / 128.0f);
    float var = q * (1.0f / 128.0f) - mu * mu;
    float rstd = rsqrtf(var + LN_EPSF);

    float4 g4 = *(const float4*)(gamma + c);
    float4 be = *(const float4*)(beta + c);
    float4 o4;
    o4.x = (v.x - mu) * rstd * g4.x + be.x;
    o4.y = (v.y - mu) * rstd * g4.y + be.y;
    o4.z = (v.z - mu) * rstd * g4.z + be.z;
    o4.w = (v.w - mu) * rstd * g4.w + be.w;
    *(float4*)(out + e * DMODEL + c) = o4;
}

// ---------------- host -------------------------------------------------------
#define SMEM_FUSED ((3 * 128 * PADF + 384) * 4 + 256 * 4)
#define SMEM_NODE  (2 * 128 * PADF * 4)

extern "C" void kernel_launch(void* const* d_in, const int* in_sizes, int n_in,
                              void* d_out, int out_size) {
    const float* X   = (const float*)d_in[0];
    const void*  idx = d_in[1];
    int base = 2;
    if (n_in >= 13 && in_sizes[2] == 1) base = 3;
    const float* Wq    = (const float*)d_in[base + 0];
    const float* bq    = (const float*)d_in[base + 1];
    const float* Wk    = (const float*)d_in[base + 2];
    const float* bk    = (const float*)d_in[base + 3];
    const float* Wv    = (const float*)d_in[base + 4];
    const float* bv    = (const float*)d_in[base + 5];
    const float* Wo    = (const float*)d_in[base + 6];
    const float* bo    = (const float*)d_in[base + 7];
    const float* gamma = (const float*)d_in[base + 8];
    const float* beta  = (const float*)d_in[base + 9];
    float* out = (float*)d_out;

    cudaFuncSetAttribute(fused_kernel, cudaFuncAttributeMaxDynamicSharedMemorySize, SMEM_FUSED);
    cudaFuncSetAttribute(nodeT_kernel, cudaFuncAttributeMaxDynamicSharedMemorySize, SMEM_NODE);

    detect_kernel<<<1, 32>>>((const int*)idx);
    init_kernel<<<8192, 256>>>();
    prep_kernel<<<dim3(4, 4, 4), dim3(32, 8)>>>(Wq, Wk, Wv, Wo);
    fused_kernel<<<E_EDGES / 128, 256, SMEM_FUSED>>>(X, idx, bq, bk, bv);
    nodeT_kernel<<<NNODES / 128, 256, SMEM_NODE>>>();
    epi_kernel<<<E_EDGES / 8, 256>>>(idx, X, bo, gamma, beta, out);
}

// round 7
// speedup vs baseline: 1.5144x; 1.0355x over previous
#include <cuda_runtime.h>

#define E_EDGES 262144
#define DMODEL  128
#define NNODES  65536
#define PADF    132
#define LN_EPSF 1e-5f
#define SCALEF  0.17677669529663687f   // 1/sqrt(32)

// ---------------- scratch (device globals; no allocations allowed) ----------
__device__ float g_S[(size_t)NNODES * DMODEL];    // sum exp(s)*V per node
__device__ float g_den[(size_t)NNODES * 4];       // sum exp(s) per node/head
__device__ float g_T[(size_t)NNODES * DMODEL];    // (0.5*S/den) @ Wo per node
__device__ float g_Wt[4][DMODEL][DMODEL];         // tf32, transposed + XOR-swizzled
__device__ int   g_is64;

// ---------------- helpers ----------------------------------------------------
__device__ __forceinline__ float to_tf32(float x) {
    float r; asm("cvt.rna.tf32.f32 %0, %1;" : "=f"(r) : "f"(x)); return r;
}

__device__ __forceinline__ void mma_tf32(float c[4], const unsigned a[4],
                                         unsigned b0, unsigned b1) {
    asm volatile(
        "mma.sync.aligned.m16n8k8.row.col.f32.tf32.tf32.f32 "
        "{%0,%1,%2,%3}, {%4,%5,%6,%7}, {%8,%9}, {%0,%1,%2,%3};"
        : "+f"(c[0]), "+f"(c[1]), "+f"(c[2]), "+f"(c[3])
        : "r"(a[0]), "r"(a[1]), "r"(a[2]), "r"(a[3]), "r"(b0), "r"(b1));
}

__device__ __forceinline__ void red_add_v4(float* p, float x, float y, float z, float w) {
    asm volatile("red.global.add.v4.f32 [%0], {%1,%2,%3,%4};"
                 :: "l"(p), "f"(x), "f"(y), "f"(z), "f"(w) : "memory");
}
__device__ __forceinline__ void red_add_v2(float* p, float x, float y) {
    asm volatile("red.global.add.v2.f32 [%0], {%1,%2};"
                 :: "l"(p), "f"(x), "f"(y) : "memory");
}

__device__ __forceinline__ void cp_async16(float* smem_dst, const float* gsrc) {
    unsigned s = (unsigned)__cvta_generic_to_shared(smem_dst);
    asm volatile("cp.async.cg.shared.global [%0], [%1], 16;" :: "r"(s), "l"(gsrc));
}
__device__ __forceinline__ void cp_commit() {
    asm volatile("cp.async.commit_group;");
}
template <int N>
__device__ __forceinline__ void cp_wait() {
    asm volatile("cp.async.wait_group %0;" :: "n"(N));
}

__device__ __forceinline__ int node_of(const void* idx, int is64, size_t pos) {
    return is64 ? (int)((const long long*)idx)[pos] : ((const int*)idx)[pos];
}

// per-warp m32 x n64 tf32 GEMM tile. A: PADF-padded (conflict-free).
// B: stride 128, XOR-swizzled (k ^ ((n&7)<<2)); n&7 == gr for every lane,
// so fragment loads hit 32 distinct banks.
__device__ __forceinline__ void gemm_tile64(const float* __restrict__ As,
                                            const float* __restrict__ Ws,
                                            float acc[2][8][4],
                                            int wm, int wn, int gr, int tg) {
    #pragma unroll
    for (int mi = 0; mi < 2; ++mi)
        #pragma unroll
        for (int ni = 0; ni < 8; ++ni)
            #pragma unroll
            for (int q = 0; q < 4; ++q) acc[mi][ni][q] = 0.f;
    #pragma unroll
    for (int kk = 0; kk < 16; ++kk) {
        int k0 = kk << 3;
        int ksw0 = (k0 + tg)     ^ (gr << 2);
        int ksw1 = (k0 + tg + 4) ^ (gr << 2);
        unsigned a[2][4];
        #pragma unroll
        for (int mi = 0; mi < 2; ++mi) {
            int r = wm * 32 + mi * 16 + gr;
            a[mi][0] = __float_as_uint(As[r * PADF + k0 + tg]);
            a[mi][1] = __float_as_uint(As[(r + 8) * PADF + k0 + tg]);
            a[mi][2] = __float_as_uint(As[r * PADF + k0 + tg + 4]);
            a[mi][3] = __float_as_uint(As[(r + 8) * PADF + k0 + tg + 4]);
        }
        #pragma unroll
        for (int ni = 0; ni < 8; ++ni) {
            int n = wn * 64 + ni * 8 + gr;
            unsigned b0 = __float_as_uint(Ws[n * 128 + ksw0]);
            unsigned b1 = __float_as_uint(Ws[n * 128 + ksw1]);
            mma_tf32(acc[0][ni], a[0], b0, b1);
            mma_tf32(acc[1][ni], a[1], b0, b1);
        }
    }
}

// ---------------- kernel 0: edge_index dtype detection ----------------------
__global__ void detect_kernel(const int* __restrict__ idx) {
    if (threadIdx.x == 0) {
        int nz = 0;
        #pragma unroll 1
        for (int i = 0; i < 64; ++i) nz |= idx[2 * i + 1];
        g_is64 = (nz == 0) ? 1 : 0;
    }
}

// ---------------- kernel 1: zero init ----------------------------------------
__global__ void init_kernel() {
    size_t i = (size_t)blockIdx.x * blockDim.x + threadIdx.x;
    if (i < (size_t)NNODES * DMODEL / 4)
        ((float4*)g_S)[i] = make_float4(0.f, 0.f, 0.f, 0.f);
    if (i < (size_t)NNODES)
        ((float4*)g_den)[i] = make_float4(0.f, 0.f, 0.f, 0.f);
}

// ---------------- kernel 2: weight prep (transpose + tf32 + swizzle, once) ---
__global__ void prep_kernel(const float* __restrict__ Wq, const float* __restrict__ Wk,
                            const float* __restrict__ Wv, const float* __restrict__ Wo) {
    __shared__ float t[32][33];
    const float* W[4] = {Wq, Wk, Wv, Wo};
    int w = blockIdx.z, k0 = blockIdx.x * 32, n0 = blockIdx.y * 32;
    int tx = threadIdx.x, ty = threadIdx.y;      // 32 x 8
    const float* src = W[w];
    #pragma unroll
    for (int j = 0; j < 32; j += 8)
        t[ty + j][tx] = to_tf32(src[(k0 + ty + j) * DMODEL + n0 + tx]);
    __syncthreads();
    #pragma unroll
    for (int j = 0; j < 32; j += 8) {
        int n = n0 + ty + j;
        int k = k0 + tx;
        int ksw = k ^ ((n & 7) << 2);
        g_Wt[w][n][ksw] = t[tx][ty + j];
    }
}

// ---------------- kernel 3: fused QKV + scores + scatter ---------------------
__global__ __launch_bounds__(256, 1)
void fused_kernel(const float* __restrict__ X, const void* __restrict__ idx,
                  const float* __restrict__ bq, const float* __restrict__ bk,
                  const float* __restrict__ bv) {
    extern __shared__ float sm[];
    float* As  = sm;                       // [128][PADF] X tile (raw fp32 -> tf32 trunc)
    float* Ws0 = sm + 128 * PADF;          // weight buffer 0 (swizzled, stride 128)
    float* Ws1 = Ws0 + 128 * 128;          // weight buffer 1
    float* sb  = Ws1 + 128 * 128;          // bq(128) bk(128) bv(128)
    int*  sidx = (int*)(sb + 384);         // src[128], dst[128]

    int tid = threadIdx.x, lane = tid & 31, warp = tid >> 5;
    int wm = warp & 3, wn = warp >> 2, gr = lane >> 2, tg = lane & 3;
    size_t e0 = (size_t)blockIdx.x * 128;
    int is64 = g_is64;

    // G0: X tile + Wq
    for (int i = tid; i < 4096; i += 256) {
        int r = i >> 5, c = (i & 31) << 2;
        cp_async16(As + r * PADF + c, X + (e0 + r) * DMODEL + c);
    }
    for (int i = tid; i < 4096; i += 256)
        cp_async16(Ws0 + i * 4, ((const float*)g_Wt[0]) + i * 4);
    cp_commit();
    // G1: Wk
    for (int i = tid; i < 4096; i += 256)
        cp_async16(Ws1 + i * 4, ((const float*)g_Wt[1]) + i * 4);
    cp_commit();

    // indices + biases while copies fly
    if (tid < 128) sidx[tid] = node_of(idx, is64, e0 + tid);
    else           sidx[tid] = node_of(idx, is64, (size_t)E_EDGES + e0 + (tid - 128));
    for (int i = tid; i < 384; i += 256)
        sb[i] = (i < 128) ? bq[i] : (i < 256 ? bk[i - 128] : bv[i - 256]);

    cp_wait<1>();      // As + Wq landed
    __syncthreads();

    float Qa[2][8][4];
    gemm_tile64(As, Ws0, Qa, wm, wn, gr, tg);    // Q
    __syncthreads();                              // done reading Ws0

    // G2: Wv into Ws0
    for (int i = tid; i < 4096; i += 256)
        cp_async16(Ws0 + i * 4, ((const float*)g_Wt[2]) + i * 4);
    cp_commit();
    cp_wait<1>();      // Wk landed
    __syncthreads();

    float acc[2][8][4];
    gemm_tile64(As, Ws1, acc, wm, wn, gr, tg);   // K

    // scores: register-local dot (Q+bq).(K+bk), quad-shuffle reduce, exp
    float ev[8];                                  // [(mi<<2)|(sr<<1)|hl]
    #pragma unroll
    for (int mi = 0; mi < 2; ++mi) {
        #pragma unroll
        for (int hl = 0; hl < 2; ++hl) {
            float s0 = 0.f, s1 = 0.f;
            #pragma unroll
            for (int j = 0; j < 4; ++j) {
                int ni = hl * 4 + j;
                int col = wn * 64 + ni * 8 + tg * 2;
                float bq0 = sb[col], bq1 = sb[col + 1];
                float bk0 = sb[128 + col], bk1 = sb[128 + col + 1];
                s0 += (Qa[mi][ni][0] + bq0) * (acc[mi][ni][0] + bk0)
                    + (Qa[mi][ni][1] + bq1) * (acc[mi][ni][1] + bk1);
                s1 += (Qa[mi][ni][2] + bq0) * (acc[mi][ni][2] + bk0)
                    + (Qa[mi][ni][3] + bq1) * (acc[mi][ni][3] + bk1);
            }
            s0 += __shfl_xor_sync(0xffffffffu, s0, 1);
            s0 += __shfl_xor_sync(0xffffffffu, s0, 2);
            s1 += __shfl_xor_sync(0xffffffffu, s1, 1);
            s1 += __shfl_xor_sync(0xffffffffu, s1, 2);
            ev[(mi << 2) | (0 << 1) | hl] = __expf(s0 * SCALEF);
            ev[(mi << 2) | (1 << 1) | hl] = __expf(s1 * SCALEF);
        }
    }

    cp_wait<0>();      // Wv landed
    __syncthreads();

    gemm_tile64(As, Ws0, acc, wm, wn, gr, tg);   // V

    // scatter from registers: weighted V to src & dst, den per head
    #pragma unroll
    for (int mi = 0; mi < 2; ++mi) {
        #pragma unroll
        for (int sr = 0; sr < 2; ++sr) {
            int row = wm * 32 + mi * 16 + sr * 8 + gr;
            int src = sidx[row], dst = sidx[128 + row];
            float* ps = g_S + (size_t)src * DMODEL;
            float* pd = g_S + (size_t)dst * DMODEL;
            if (tg == 0) {
                float e0h = ev[(mi << 2) | (sr << 1)];
                float e1h = ev[(mi << 2) | (sr << 1) | 1];
                red_add_v2(&g_den[(size_t)src * 4 + wn * 2], e0h, e1h);
                red_add_v2(&g_den[(size_t)dst * 4 + wn * 2], e0h, e1h);
            }
            #pragma unroll
            for (int ni = 0; ni < 8; ++ni) {
                int col = wn * 64 + ni * 8 + tg * 2;
                float w = ev[(mi << 2) | (sr << 1) | (ni >> 2)];
                float v0 = (acc[mi][ni][sr * 2]     + sb[256 + col])     * w;
                float v1 = (acc[mi][ni][sr * 2 + 1] + sb[256 + col + 1]) * w;
                float p0 = __shfl_xor_sync(0xffffffffu, v0, 1);
                float p1 = __shfl_xor_sync(0xffffffffu, v1, 1);
                if (!(tg & 1)) {
                    red_add_v4(ps + col, v0, v1, p0, p1);
                    red_add_v4(pd + col, v0, v1, p0, p1);
                }
            }
        }
    }
}

// ---------------- kernel 4: per-NODE Wo GEMM: T = (0.5*S/den) @ Wo -----------
__global__ __launch_bounds__(256, 1)
void nodeT_kernel() {
    extern __shared__ float sm[];
    float* Ms = sm;                       // node msg tile (PADF-padded)
    float* Ws = sm + 128 * PADF;          // Wo^T tf32, swizzled, stride 128

    int tid = threadIdx.x, lane = tid & 31, warp = tid >> 5;
    int wm = warp & 3, wn = warp >> 2, gr = lane >> 2, tg = lane & 3;
    size_t n0 = (size_t)blockIdx.x * 128;

    for (int i = tid; i < 4096; i += 256)
        cp_async16(Ws + i * 4, ((const float*)g_Wt[3]) + i * 4);
    cp_commit();

    {   // build tile: 2 threads per node row, 64 cols each
        int r = tid >> 1, hf = tid & 1;
        size_t node = n0 + r;
        float d0 = g_den[node * 4 + hf * 2], d1 = g_den[node * 4 + hf * 2 + 1];
        float f0 = (d0 > 0.f) ? 0.5f / d0 : 0.f;
        float f1 = (d1 > 0.f) ? 0.5f / d1 : 0.f;
        const float* Sp = g_S + node * DMODEL + hf * 64;
        #pragma unroll
        for (int j = 0; j < 16; ++j) {
            int c = j * 4;
            float f = (c < 32) ? f0 : f1;
            float4 a = *(const float4*)(Sp + c);
            int cc = hf * 64 + c;
            Ms[r * PADF + cc + 0] = a.x * f;
            Ms[r * PADF + cc + 1] = a.y * f;
            Ms[r * PADF + cc + 2] = a.z * f;
            Ms[r * PADF + cc + 3] = a.w * f;
        }
    }
    cp_wait<0>();
    __syncthreads();

    float acc[2][8][4];
    gemm_tile64(Ms, Ws, acc, wm, wn, gr, tg);

    #pragma unroll
    for (int mi = 0; mi < 2; ++mi) {
        int r0 = wm * 32 + mi * 16 + gr;
        #pragma unroll
        for (int ni = 0; ni < 8; ++ni) {
            int col = wn * 64 + ni * 8 + tg * 2;
            *(float2*)(g_T + (n0 + r0) * DMODEL + col)       = make_float2(acc[mi][ni][0], acc[mi][ni][1]);
            *(float2*)(g_T + (n0 + r0 + 8) * DMODEL + col)   = make_float2(acc[mi][ni][2], acc[mi][ni][3]);
        }
    }
}

// ---------------- kernel 5: edge epilogue: LN(T[src]+T[dst]+bo+X) ------------
__global__ __launch_bounds__(256)
void epi_kernel(const void* __restrict__ idx, const float* __restrict__ X,
                const float* __restrict__ bo, const float* __restrict__ gamma,
                const float* __restrict__ beta, float* __restrict__ out) {
    int tid = threadIdx.x, lane = tid & 31;
    size_t e = (size_t)blockIdx.x * 8 + (tid >> 5);
    int is64 = g_is64;

    int src = node_of(idx, is64, e);
    int dst = node_of(idx, is64, (size_t)E_EDGES + e);

    int c = lane * 4;
    float4 ts = *(const float4*)(g_T + (size_t)src * DMODEL + c);
    float4 td = *(const float4*)(g_T + (size_t)dst * DMODEL + c);
    float4 x4 = *(const float4*)(X + e * DMODEL + c);
    float4 b4 = *(const float4*)(bo + c);

    float4 v;
    v.x = ts.x + td.x + b4.x + x4.x;
    v.y = ts.y + td.y + b4.y + x4.y;
    v.z = ts.z + td.z + b4.z + x4.z;
    v.w = ts.w + td.w + b4.w + x4.w;

    float s = v.x + v.y + v.z + v.w;
    float q = v.x * v.x + v.y * v.y + v.z * v.z + v.w * v.w;
    #pragma unroll
    for (int o = 16; o > 0; o >>= 1) {
        s += __shfl_xor_sync(0xffffffffu, s, o);
        q += __shfl_xor_sync(0xffffffffu, q, o);
    }
    float mu = s * (1.0f / 128.0f);
    float var = q * (1.0f / 128.0f) - mu * mu;
    float rstd = rsqrtf(var + LN_EPSF);

    float4 g4 = *(const float4*)(gamma + c);
    float4 be = *(const float4*)(beta + c);
    float4 o4;
    o4.x = (v.x - mu) * rstd * g4.x + be.x;
    o4.y = (v.y - mu) * rstd * g4.y + be.y;
    o4.z = (v.z - mu) * rstd * g4.z + be.z;
    o4.w = (v.w - mu) * rstd * g4.w + be.w;
    *(float4*)(out + e * DMODEL + c) = o4;
}

// ---------------- host -------------------------------------------------------
#define SMEM_FUSED ((128 * PADF + 2 * 128 * 128 + 384) * 4 + 256 * 4)
#define SMEM_NODE  ((128 * PADF + 128 * 128) * 4)

extern "C" void kernel_launch(void* const* d_in, const int* in_sizes, int n_in,
                              void* d_out, int out_size) {
    const float* X   = (const float*)d_in[0];
    const void*  idx = d_in[1];
    int base = 2;
    if (n_in >= 13 && in_sizes[2] == 1) base = 3;
    const float* Wq    = (const float*)d_in[base + 0];
    const float* bq    = (const float*)d_in[base + 1];
    const float* Wk    = (const float*)d_in[base + 2];
    const float* bk    = (const float*)d_in[base + 3];
    const float* Wv    = (const float*)d_in[base + 4];
    const float* bv    = (const float*)d_in[base + 5];
    const float* Wo    = (const float*)d_in[base + 6];
    const float* bo    = (const float*)d_in[base + 7];
    const float* gamma = (const float*)d_in[base + 8];
    const float* beta  = (const float*)d_in[base + 9];
    float* out = (float*)d_out;

    cudaFuncSetAttribute(fused_kernel, cudaFuncAttributeMaxDynamicSharedMemorySize, SMEM_FUSED);
    cudaFuncSetAttribute(nodeT_kernel, cudaFuncAttributeMaxDynamicSharedMemorySize, SMEM_NODE);

    detect_kernel<<<1, 32>>>((const int*)idx);
    init_kernel<<<8192, 256>>>();
    prep_kernel<<<dim3(4, 4, 4), dim3(32, 8)>>>(Wq, Wk, Wv, Wo);
    fused_kernel<<<E_EDGES / 128, 256, SMEM_FUSED>>>(X, idx, bq, bk, bv);
    nodeT_kernel<<<NNODES / 128, 256, SMEM_NODE>>>();
    epi_kernel<<<E_EDGES / 8, 256>>>(idx, X, bo, gamma, beta, out);
}

// round 8
// speedup vs baseline: 1.6368x; 1.0808x over previous
#include <cuda_runtime.h>

#define E_EDGES 262144
#define DMODEL  128
#define NNODES  65536
#define PADF    132
#define LN_EPSF 1e-5f
#define SCALEF  0.17677669529663687f   // 1/sqrt(32)
#define NTILES  4096                   // 64-edge tiles
#define PGRID   152

// ---------------- scratch (device globals; no allocations allowed) ----------
__device__ float g_S[(size_t)NNODES * DMODEL];    // sum exp(s)*V per node
__device__ float g_den[(size_t)NNODES * 4];       // sum exp(s) per node/head
__device__ float g_T[(size_t)NNODES * DMODEL];    // (0.5*S/den) @ Wo per node
__device__ float g_Wt[4][DMODEL][DMODEL];         // tf32; 0..2: perm+swz8, 3: swz4
__device__ int   g_is64;

// ---------------- helpers ----------------------------------------------------
__device__ __forceinline__ float to_tf32(float x) {
    float r; asm("cvt.rna.tf32.f32 %0, %1;" : "=f"(r) : "f"(x)); return r;
}

__device__ __forceinline__ void mma_tf32(float c[4], const unsigned a[4],
                                         unsigned b0, unsigned b1) {
    asm volatile(
        "mma.sync.aligned.m16n8k8.row.col.f32.tf32.tf32.f32 "
        "{%0,%1,%2,%3}, {%4,%5,%6,%7}, {%8,%9}, {%0,%1,%2,%3};"
        : "+f"(c[0]), "+f"(c[1]), "+f"(c[2]), "+f"(c[3])
        : "r"(a[0]), "r"(a[1]), "r"(a[2]), "r"(a[3]), "r"(b0), "r"(b1));
}

__device__ __forceinline__ void red_add_v4(float* p, float x, float y, float z, float w) {
    asm volatile("red.global.add.v4.f32 [%0], {%1,%2,%3,%4};"
                 :: "l"(p), "f"(x), "f"(y), "f"(z), "f"(w) : "memory");
}
__device__ __forceinline__ void red_add_f(float* p, float v) {
    asm volatile("red.global.add.f32 [%0], %1;" :: "l"(p), "f"(v) : "memory");
}

__device__ __forceinline__ void cp_async16(float* smem_dst, const float* gsrc) {
    unsigned s = (unsigned)__cvta_generic_to_shared(smem_dst);
    asm volatile("cp.async.cg.shared.global [%0], [%1], 16;" :: "r"(s), "l"(gsrc));
}
__device__ __forceinline__ void cp_commit() {
    asm volatile("cp.async.commit_group;");
}
template <int N>
__device__ __forceinline__ void cp_wait() {
    asm volatile("cp.async.wait_group %0;" :: "n"(N));
}

__device__ __forceinline__ int node_of(const void* idx, int is64, size_t pos) {
    return is64 ? (int)__ldg((const long long*)idx + pos)
                : __ldg((const int*)idx + pos);
}

// ---------------- kernel 0: edge_index dtype detection ----------------------
__global__ void detect_kernel(const int* __restrict__ idx) {
    if (threadIdx.x == 0) {
        int nz = 0;
        #pragma unroll 1
        for (int i = 0; i < 64; ++i) nz |= idx[2 * i + 1];
        g_is64 = (nz == 0) ? 1 : 0;
    }
}

// ---------------- kernel 1: zero init ----------------------------------------
__global__ void init_kernel() {
    size_t i = (size_t)blockIdx.x * blockDim.x + threadIdx.x;
    if (i < (size_t)NNODES * DMODEL / 4)
        ((float4*)g_S)[i] = make_float4(0.f, 0.f, 0.f, 0.f);
    if (i < (size_t)NNODES)
        ((float4*)g_den)[i] = make_float4(0.f, 0.f, 0.f, 0.f);
}

// ---------------- kernel 2: weight prep (transpose + tf32 + swizzle, once) ---
// w<3 (Wq,Wk,Wv): k' = perm(k) ^ ((n&7)<<3), perm pairs k and k+4 adjacent.
// w==3 (Wo):      k' = k ^ ((n&7)<<2)  (layout used by nodeT's gemm_tile64)
__global__ void prep_kernel(const float* __restrict__ Wq, const float* __restrict__ Wk,
                            const float* __restrict__ Wv, const float* __restrict__ Wo) {
    __shared__ float t[32][33];
    const float* W[4] = {Wq, Wk, Wv, Wo};
    int w = blockIdx.z, k0 = blockIdx.x * 32, n0 = blockIdx.y * 32;
    int tx = threadIdx.x, ty = threadIdx.y;      // 32 x 8
    const float* src = W[w];
    #pragma unroll
    for (int j = 0; j < 32; j += 8)
        t[ty + j][tx] = to_tf32(src[(k0 + ty + j) * DMODEL + n0 + tx]);
    __syncthreads();
    #pragma unroll
    for (int j = 0; j < 32; j += 8) {
        int n = n0 + ty + j;
        int k = k0 + tx;
        int ksw;
        if (w < 3) {
            int kp = (k & ~7) | ((k & 3) << 1) | ((k >> 2) & 1);
            ksw = kp ^ ((n & 7) << 3);
        } else {
            ksw = k ^ ((n & 7) << 2);
        }
        g_Wt[w][n][ksw] = t[tx][ty + j];
    }
}

// ---------------- kernel 3: persistent fused QKV + scores + scatter ----------
// 152 CTAs x 256 thr; weights resident in smem; 64-edge tiles; 3 GEMMs fused
// into one kk loop. Warp grid 2m x 4n, per-warp m32 x n32 (wn == head).
__global__ __launch_bounds__(256, 1)
void fusedP_kernel(const float* __restrict__ X, const void* __restrict__ idx,
                   const float* __restrict__ bq, const float* __restrict__ bk,
                   const float* __restrict__ bv) {
    extern __shared__ float sm[];
    float* As = sm;                  // [64][128] swizzled X tile
    float* Wq_ = sm + 64 * 128;      // 3 x [128][128] swizzled weights
    float* Wk_ = Wq_ + 128 * 128;
    float* Wv_ = Wk_ + 128 * 128;

    int tid = threadIdx.x, lane = tid & 31, warp = tid >> 5;
    int wm = warp & 1, wn = warp >> 1, gr = lane >> 2, tg = lane & 3;
    int is64 = g_is64;

    // one-time: all three weight matrices (g_Wt[0..2] are contiguous)
    for (int i = tid; i < 3 * 4096; i += 256)
        cp_async16(Wq_ + i * 4, ((const float*)g_Wt) + i * 4);
    // first A tile
    {
        size_t e0 = (size_t)blockIdx.x * 64;
        for (int i = tid; i < 2048; i += 256) {
            int r = i >> 5, c = (i & 31) << 2;
            cp_async16(As + r * 128 + (c ^ ((r & 7) << 2)),
                       X + (e0 + r) * DMODEL + c);
        }
    }
    cp_commit();
    cp_wait<0>();
    __syncthreads();

    int pr = tid >> 2, pc = tid & 3;

    for (int t = blockIdx.x; t < NTILES; t += gridDim.x) {
        int tn = t + gridDim.x;
        bool hasNext = tn < NTILES;
        float4 Xn[8];
        if (hasNext) {
            const float4* Xb = (const float4*)(X + ((size_t)tn * 64 + pr) * DMODEL);
            #pragma unroll
            for (int j = 0; j < 8; ++j) Xn[j] = __ldg(Xb + pc + j * 4);
        }
        size_t e0 = (size_t)t * 64;

        // ---- triple GEMM over kk: acc[0]=Q, acc[1]=K, acc[2]=V ----
        float acc[3][2][4][4];
        #pragma unroll
        for (int g = 0; g < 3; ++g)
            #pragma unroll
            for (int mi = 0; mi < 2; ++mi)
                #pragma unroll
                for (int ni = 0; ni < 4; ++ni)
                    #pragma unroll
                    for (int q = 0; q < 4; ++q) acc[g][mi][ni][q] = 0.f;

        #pragma unroll
        for (int kk = 0; kk < 16; ++kk) {
            int k0 = kk << 3;
            int kswA0 = (k0 + tg)     ^ (gr << 2);
            int kswA1 = (k0 + tg + 4) ^ (gr << 2);
            int kswB  = (k0 + (tg << 1)) ^ (gr << 3);
            unsigned a[2][4];
            #pragma unroll
            for (int mi = 0; mi < 2; ++mi) {
                int r = wm * 32 + mi * 16 + gr;
                a[mi][0] = __float_as_uint(As[r * 128 + kswA0]);
                a[mi][1] = __float_as_uint(As[(r + 8) * 128 + kswA0]);
                a[mi][2] = __float_as_uint(As[r * 128 + kswA1]);
                a[mi][3] = __float_as_uint(As[(r + 8) * 128 + kswA1]);
            }
            const float* Wg[3] = {Wq_, Wk_, Wv_};
            #pragma unroll
            for (int g = 0; g < 3; ++g) {
                #pragma unroll
                for (int ni = 0; ni < 4; ++ni) {
                    int n = wn * 32 + ni * 8 + gr;
                    float2 b = *(const float2*)(Wg[g] + n * 128 + kswB);
                    unsigned b0 = __float_as_uint(b.x), b1 = __float_as_uint(b.y);
                    mma_tf32(acc[g][0][ni], a[0], b0, b1);
                    mma_tf32(acc[g][1][ni], a[1], b0, b1);
                }
            }
        }

        // ---- scores for head wn: (Q+bq).(K+bk), quad shuffle, exp ----
        float ev[4];
        #pragma unroll
        for (int mi = 0; mi < 2; ++mi) {
            float s0 = 0.f, s1 = 0.f;
            #pragma unroll
            for (int ni = 0; ni < 4; ++ni) {
                int col = wn * 32 + ni * 8 + tg * 2;
                float bq0 = __ldg(bq + col), bq1 = __ldg(bq + col + 1);
                float bk0 = __ldg(bk + col), bk1 = __ldg(bk + col + 1);
                s0 += (acc[0][mi][ni][0] + bq0) * (acc[1][mi][ni][0] + bk0)
                    + (acc[0][mi][ni][1] + bq1) * (acc[1][mi][ni][1] + bk1);
                s1 += (acc[0][mi][ni][2] + bq0) * (acc[1][mi][ni][2] + bk0)
                    + (acc[0][mi][ni][3] + bq1) * (acc[1][mi][ni][3] + bk1);
            }
            s0 += __shfl_xor_sync(0xffffffffu, s0, 1);
            s0 += __shfl_xor_sync(0xffffffffu, s0, 2);
            s1 += __shfl_xor_sync(0xffffffffu, s1, 1);
            s1 += __shfl_xor_sync(0xffffffffu, s1, 2);
            ev[mi * 2]     = __expf(s0 * SCALEF);
            ev[mi * 2 + 1] = __expf(s1 * SCALEF);
        }

        // ---- scatter: weighted V to src & dst, den per head ----
        #pragma unroll
        for (int mi = 0; mi < 2; ++mi) {
            #pragma unroll
            for (int sr = 0; sr < 2; ++sr) {
                int row = wm * 32 + mi * 16 + sr * 8 + gr;
                size_t e = e0 + row;
                int src = node_of(idx, is64, e);
                int dst = node_of(idx, is64, (size_t)E_EDGES + e);
                float* ps = g_S + (size_t)src * DMODEL;
                float* pd = g_S + (size_t)dst * DMODEL;
                float w = ev[mi * 2 + sr];
                if (tg == 0) {
                    red_add_f(&g_den[(size_t)src * 4 + wn], w);
                    red_add_f(&g_den[(size_t)dst * 4 + wn], w);
                }
                #pragma unroll
                for (int ni = 0; ni < 4; ++ni) {
                    int col = wn * 32 + ni * 8 + tg * 2;
                    float v0 = (acc[2][mi][ni][sr * 2]     + __ldg(bv + col))     * w;
                    float v1 = (acc[2][mi][ni][sr * 2 + 1] + __ldg(bv + col + 1)) * w;
                    float p0 = __shfl_xor_sync(0xffffffffu, v0, 1);
                    float p1 = __shfl_xor_sync(0xffffffffu, v1, 1);
                    if (!(tg & 1)) {
                        red_add_v4(ps + col, v0, v1, p0, p1);
                        red_add_v4(pd + col, v0, v1, p0, p1);
                    }
                }
            }
        }

        __syncthreads();   // everyone done reading As
        if (hasNext) {
            #pragma unroll
            for (int j = 0; j < 8; ++j) {
                int c = (pc + j * 4) << 2;
                *(float4*)(As + pr * 128 + (c ^ ((pr & 7) << 2))) = Xn[j];
            }
        }
        __syncthreads();   // As refilled
    }
}

// per-warp m32 x n64 tf32 GEMM tile for nodeT (R7 layout: Wo swz ^(n&7)<<2)
__device__ __forceinline__ void gemm_tile64(const float* __restrict__ As,
                                            const float* __restrict__ Ws,
                                            float acc[2][8][4],
                                            int wm, int wn, int gr, int tg) {
    #pragma unroll
    for (int mi = 0; mi < 2; ++mi)
        #pragma unroll
        for (int ni = 0; ni < 8; ++ni)
            #pragma unroll
            for (int q = 0; q < 4; ++q) acc[mi][ni][q] = 0.f;
    #pragma unroll
    for (int kk = 0; kk < 16; ++kk) {
        int k0 = kk << 3;
        int ksw0 = (k0 + tg)     ^ (gr << 2);
        int ksw1 = (k0 + tg + 4) ^ (gr << 2);
        unsigned a[2][4];
        #pragma unroll
        for (int mi = 0; mi < 2; ++mi) {
            int r = wm * 32 + mi * 16 + gr;
            a[mi][0] = __float_as_uint(As[r * PADF + k0 + tg]);
            a[mi][1] = __float_as_uint(As[(r + 8) * PADF + k0 + tg]);
            a[mi][2] = __float_as_uint(As[r * PADF + k0 + tg + 4]);
            a[mi][3] = __float_as_uint(As[(r + 8) * PADF + k0 + tg + 4]);
        }
        #pragma unroll
        for (int ni = 0; ni < 8; ++ni) {
            int n = wn * 64 + ni * 8 + gr;
            unsigned b0 = __float_as_uint(Ws[n * 128 + ksw0]);
            unsigned b1 = __float_as_uint(Ws[n * 128 + ksw1]);
            mma_tf32(acc[0][ni], a[0], b0, b1);
            mma_tf32(acc[1][ni], a[1], b0, b1);
        }
    }
}

// ---------------- kernel 4: per-NODE Wo GEMM: T = (0.5*S/den) @ Wo -----------
__global__ __launch_bounds__(256, 1)
void nodeT_kernel() {
    extern __shared__ float sm[];
    float* Ms = sm;                       // node msg tile (PADF-padded)
    float* Ws = sm + 128 * PADF;          // Wo^T tf32, swizzled, stride 128

    int tid = threadIdx.x, lane = tid & 31, warp = tid >> 5;
    int wm = warp & 3, wn = warp >> 2, gr = lane >> 2, tg = lane & 3;
    size_t n0 = (size_t)blockIdx.x * 128;

    for (int i = tid; i < 4096; i += 256)
        cp_async16(Ws + i * 4, ((const float*)g_Wt[3]) + i * 4);
    cp_commit();

    {   // build tile: 2 threads per node row, 64 cols each
        int r = tid >> 1, hf = tid & 1;
        size_t node = n0 + r;
        float d0 = g_den[node * 4 + hf * 2], d1 = g_den[node * 4 + hf * 2 + 1];
        float f0 = (d0 > 0.f) ? 0.5f / d0 : 0.f;
        float f1 = (d1 > 0.f) ? 0.5f / d1 : 0.f;
        const float* Sp = g_S + node * DMODEL + hf * 64;
        #pragma unroll
        for (int j = 0; j < 16; ++j) {
            int c = j * 4;
            float f = (c < 32) ? f0 : f1;
            float4 a = *(const float4*)(Sp + c);
            int cc = hf * 64 + c;
            Ms[r * PADF + cc + 0] = a.x * f;
            Ms[r * PADF + cc + 1] = a.y * f;
            Ms[r * PADF + cc + 2] = a.z * f;
            Ms[r * PADF + cc + 3] = a.w * f;
        }
    }
    cp_wait<0>();
    __syncthreads();

    float acc[2][8][4];
    gemm_tile64(Ms, Ws, acc, wm, wn, gr, tg);

    #pragma unroll
    for (int mi = 0; mi < 2; ++mi) {
        int r0 = wm * 32 + mi * 16 + gr;
        #pragma unroll
        for (int ni = 0; ni < 8; ++ni) {
            int col = wn * 64 + ni * 8 + tg * 2;
            *(float2*)(g_T + (n0 + r0) * DMODEL + col)       = make_float2(acc[mi][ni][0], acc[mi][ni][1]);
            *(float2*)(g_T + (n0 + r0 + 8) * DMODEL + col)   = make_float2(acc[mi][ni][2], acc[mi][ni][3]);
        }
    }
}

// ---------------- kernel 5: edge epilogue: LN(T[src]+T[dst]+bo+X) ------------
__global__ __launch_bounds__(256)
void epi_kernel(const void* __restrict__ idx, const float* __restrict__ X,
                const float* __restrict__ bo, const float* __restrict__ gamma,
                const float* __restrict__ beta, float* __restrict__ out) {
    int tid = threadIdx.x, lane = tid & 31;
    size_t e = (size_t)blockIdx.x * 8 + (tid >> 5);
    int is64 = g_is64;

    int src = node_of(idx, is64, e);
    int dst = node_of(idx, is64, (size_t)E_EDGES + e);

    int c = lane * 4;
    float4 ts = *(const float4*)(g_T + (size_t)src * DMODEL + c);
    float4 td = *(const float4*)(g_T + (size_t)dst * DMODEL + c);
    float4 x4 = *(const float4*)(X + e * DMODEL + c);
    float4 b4 = *(const float4*)(bo + c);

    float4 v;
    v.x = ts.x + td.x + b4.x + x4.x;
    v.y = ts.y + td.y + b4.y + x4.y;
    v.z = ts.z + td.z + b4.z + x4.z;
    v.w = ts.w + td.w + b4.w + x4.w;

    float s = v.x + v.y + v.z + v.w;
    float q = v.x * v.x + v.y * v.y + v.z * v.z + v.w * v.w;
    #pragma unroll
    for (int o = 16; o > 0; o >>= 1) {
        s += __shfl_xor_sync(0xffffffffu, s, o);
        q += __shfl_xor_sync(0xffffffffu, q, o);
    }
    float mu = s * (1.0f / 128.0f);
    float var = q * (1.0f / 128.0f) - mu * mu;
    float rstd = rsqrtf(var + LN_EPSF);

    float4 g4 = *(const float4*)(gamma + c);
    float4 be = *(const float4*)(beta + c);
    float4 o4;
    o4.x = (v.x - mu) * rstd * g4.x + be.x;
    o4.y = (v.y - mu) * rstd * g4.y + be.y;
    o4.z = (v.z - mu) * rstd * g4.z + be.z;
    o4.w = (v.w - mu) * rstd * g4.w + be.w;
    *(float4*)(out + e * DMODEL + c) = o4;
}

// ---------------- host -------------------------------------------------------
#define SMEM_P     ((64 * 128 + 3 * 128 * 128) * 4)
#define SMEM_NODE  ((128 * PADF + 128 * 128) * 4)

extern "C" void kernel_launch(void* const* d_in, const int* in_sizes, int n_in,
                              void* d_out, int out_size) {
    const float* X   = (const float*)d_in[0];
    const void*  idx = d_in[1];
    int base = 2;
    if (n_in >= 13 && in_sizes[2] == 1) base = 3;
    const float* Wq    = (const float*)d_in[base + 0];
    const float* bq    = (const float*)d_in[base + 1];
    const float* Wk    = (const float*)d_in[base + 2];
    const float* bk    = (const float*)d_in[base + 3];
    const float* Wv    = (const float*)d_in[base + 4];
    const float* bv    = (const float*)d_in[base + 5];
    const float* Wo    = (const float*)d_in[base + 6];
    const float* bo    = (const float*)d_in[base + 7];
    const float* gamma = (const float*)d_in[base + 8];
    const float* beta  = (const float*)d_in[base + 9];
    float* out = (float*)d_out;

    cudaFuncSetAttribute(fusedP_kernel, cudaFuncAttributeMaxDynamicSharedMemorySize, SMEM_P);
    cudaFuncSetAttribute(nodeT_kernel,  cudaFuncAttributeMaxDynamicSharedMemorySize, SMEM_NODE);

    detect_kernel<<<1, 32>>>((const int*)idx);
    init_kernel<<<8192, 256>>>();
    prep_kernel<<<dim3(4, 4, 4), dim3(32, 8)>>>(Wq, Wk, Wv, Wo);
    fusedP_kernel<<<PGRID, 256, SMEM_P>>>(X, idx, bq, bk, bv);
    nodeT_kernel<<<NNODES / 128, 256, SMEM_NODE>>>();
    epi_kernel<<<E_EDGES / 8, 256>>>(idx, X, bo, gamma, beta, out);
}

// round 9
// speedup vs baseline: 1.6945x; 1.0353x over previous
#include <cuda_runtime.h>

#define E_EDGES 262144
#define DMODEL  128
#define NNODES  65536
#define LN_EPSF 1e-5f
#define SCALEF  0.17677669529663687f   // 1/sqrt(32)
#define NTILES  4096                   // 64-edge tiles
#define PGRID   152

// ---------------- scratch (device globals; no allocations allowed) ----------
__device__ float g_S[(size_t)NNODES * DMODEL];    // sum exp(s)*V per node
__device__ float g_den[(size_t)NNODES * 4];       // sum exp(s) per node/head
__device__ float g_T[(size_t)NNODES * DMODEL];    // (0.5*S/den) @ Wo per node
__device__ float g_Wt[4][DMODEL][DMODEL];         // tf32, transposed, paired-k swizzle
__device__ int   g_is64;

// ---------------- helpers ----------------------------------------------------
__device__ __forceinline__ float to_tf32(float x) {
    float r; asm("cvt.rna.tf32.f32 %0, %1;" : "=f"(r) : "f"(x)); return r;
}

__device__ __forceinline__ void mma_tf32(float c[4], const unsigned a[4],
                                         unsigned b0, unsigned b1) {
    asm volatile(
        "mma.sync.aligned.m16n8k8.row.col.f32.tf32.tf32.f32 "
        "{%0,%1,%2,%3}, {%4,%5,%6,%7}, {%8,%9}, {%0,%1,%2,%3};"
        : "+f"(c[0]), "+f"(c[1]), "+f"(c[2]), "+f"(c[3])
        : "r"(a[0]), "r"(a[1]), "r"(a[2]), "r"(a[3]), "r"(b0), "r"(b1));
}

__device__ __forceinline__ void red_add_v4(float* p, float x, float y, float z, float w) {
    asm volatile("red.global.add.v4.f32 [%0], {%1,%2,%3,%4};"
                 :: "l"(p), "f"(x), "f"(y), "f"(z), "f"(w) : "memory");
}
__device__ __forceinline__ void red_add_f(float* p, float v) {
    asm volatile("red.global.add.f32 [%0], %1;" :: "l"(p), "f"(v) : "memory");
}

__device__ __forceinline__ void cp_async16(float* smem_dst, const float* gsrc) {
    unsigned s = (unsigned)__cvta_generic_to_shared(smem_dst);
    asm volatile("cp.async.cg.shared.global [%0], [%1], 16;" :: "r"(s), "l"(gsrc));
}
__device__ __forceinline__ void cp_commit() {
    asm volatile("cp.async.commit_group;");
}
template <int N>
__device__ __forceinline__ void cp_wait() {
    asm volatile("cp.async.wait_group %0;" :: "n"(N));
}

__device__ __forceinline__ int node_of(const void* idx, int is64, size_t pos) {
    return is64 ? (int)__ldg((const long long*)idx + pos)
                : __ldg((const int*)idx + pos);
}

// Unified tf32 GEMM core: 64-row A tile (swizzled ^((r&7)<<2)), G weight
// matrices in paired-k layout. Warp grid 2m x 4n, per-warp m32 x n32.
// B: one LDS.128 per (g, ni) covers TWO kk steps, conflict-free.
template <int G>
__device__ __forceinline__ void gemm_multi(const float* __restrict__ As,
                                           const float* __restrict__ W0,
                                           const float* __restrict__ W1,
                                           const float* __restrict__ W2,
                                           float acc[][2][4][4],
                                           int wm, int wn, int gr, int tg) {
    const float* Wg[3] = {W0, W1, W2};
    #pragma unroll
    for (int g = 0; g < G; ++g)
        #pragma unroll
        for (int mi = 0; mi < 2; ++mi)
            #pragma unroll
            for (int ni = 0; ni < 4; ++ni)
                #pragma unroll
                for (int q = 0; q < 4; ++q) acc[g][mi][ni][q] = 0.f;

    #pragma unroll
    for (int p = 0; p < 8; ++p) {
        float4 bf[G][4];
        #pragma unroll
        for (int g = 0; g < G; ++g)
            #pragma unroll
            for (int ni = 0; ni < 4; ++ni) {
                int n = wn * 32 + ni * 8 + gr;
                bf[g][ni] = *(const float4*)(Wg[g] + n * 128 +
                              ((p * 16 + 4 * tg) ^ ((n & 1) << 4)));
            }
        #pragma unroll
        for (int kh = 0; kh < 2; ++kh) {
            int k0 = p * 16 + kh * 8;
            int kswA0 = (k0 + tg)     ^ (gr << 2);
            int kswA1 = (k0 + tg + 4) ^ (gr << 2);
            unsigned a[2][4];
            #pragma unroll
            for (int mi = 0; mi < 2; ++mi) {
                int r = wm * 32 + mi * 16 + gr;
                a[mi][0] = __float_as_uint(As[r * 128 + kswA0]);
                a[mi][1] = __float_as_uint(As[(r + 8) * 128 + kswA0]);
                a[mi][2] = __float_as_uint(As[r * 128 + kswA1]);
                a[mi][3] = __float_as_uint(As[(r + 8) * 128 + kswA1]);
            }
            #pragma unroll
            for (int g = 0; g < G; ++g)
                #pragma unroll
                for (int ni = 0; ni < 4; ++ni) {
                    unsigned b0 = __float_as_uint(kh ? bf[g][ni].z : bf[g][ni].x);
                    unsigned b1 = __float_as_uint(kh ? bf[g][ni].w : bf[g][ni].y);
                    mma_tf32(acc[g][0][ni], a[0], b0, b1);
                    mma_tf32(acc[g][1][ni], a[1], b0, b1);
                }
        }
    }
}

// ---------------- kernel 0: edge_index dtype detection ----------------------
__global__ void detect_kernel(const int* __restrict__ idx) {
    if (threadIdx.x == 0) {
        int nz = 0;
        #pragma unroll 1
        for (int i = 0; i < 64; ++i) nz |= idx[2 * i + 1];
        g_is64 = (nz == 0) ? 1 : 0;
    }
}

// ---------------- kernel 1: zero init ----------------------------------------
__global__ void init_kernel() {
    size_t i = (size_t)blockIdx.x * blockDim.x + threadIdx.x;
    if (i < (size_t)NNODES * DMODEL / 4)
        ((float4*)g_S)[i] = make_float4(0.f, 0.f, 0.f, 0.f);
    if (i < (size_t)NNODES)
        ((float4*)g_den)[i] = make_float4(0.f, 0.f, 0.f, 0.f);
}

// ---------------- kernel 2: weight prep --------------------------------------
// transpose + tf32 + paired-k permutation + bank swizzle (all 4 matrices):
// perm(k) = (k&~15) | ((k&3)<<2) | (((k>>3)&1)<<1) | ((k>>2)&1); ^((n&1)<<4)
__global__ void prep_kernel(const float* __restrict__ Wq, const float* __restrict__ Wk,
                            const float* __restrict__ Wv, const float* __restrict__ Wo) {
    __shared__ float t[32][33];
    const float* W[4] = {Wq, Wk, Wv, Wo};
    int w = blockIdx.z, k0 = blockIdx.x * 32, n0 = blockIdx.y * 32;
    int tx = threadIdx.x, ty = threadIdx.y;      // 32 x 8
    const float* src = W[w];
    #pragma unroll
    for (int j = 0; j < 32; j += 8)
        t[ty + j][tx] = to_tf32(src[(k0 + ty + j) * DMODEL + n0 + tx]);
    __syncthreads();
    #pragma unroll
    for (int j = 0; j < 32; j += 8) {
        int n = n0 + ty + j;
        int k = k0 + tx;
        int kp = (k & ~15) | ((k & 3) << 2) | (((k >> 3) & 1) << 1) | ((k >> 2) & 1);
        g_Wt[w][n][kp ^ ((n & 1) << 4)] = t[tx][ty + j];
    }
}

// ---------------- kernel 3: persistent fused QKV + scores + scatter ----------
__global__ __launch_bounds__(256, 1)
void fusedP_kernel(const float* __restrict__ X, const void* __restrict__ idx,
                   const float* __restrict__ bq, const float* __restrict__ bk,
                   const float* __restrict__ bv) {
    extern __shared__ float sm[];
    float* As = sm;                  // [64][128] swizzled X tile
    float* Wq_ = sm + 64 * 128;      // 3 x [128][128] paired-k weights
    float* Wk_ = Wq_ + 128 * 128;
    float* Wv_ = Wk_ + 128 * 128;

    int tid = threadIdx.x, lane = tid & 31, warp = tid >> 5;
    int wm = warp & 1, wn = warp >> 1, gr = lane >> 2, tg = lane & 3;
    int is64 = g_is64;

    // one-time: weights + first A tile
    for (int i = tid; i < 3 * 4096; i += 256)
        cp_async16(Wq_ + i * 4, ((const float*)g_Wt) + i * 4);
    {
        size_t e0 = (size_t)blockIdx.x * 64;
        for (int i = tid; i < 2048; i += 256) {
            int r = i >> 5, c = (i & 31) << 2;
            cp_async16(As + r * 128 + (c ^ ((r & 7) << 2)),
                       X + (e0 + r) * DMODEL + c);
        }
    }
    cp_commit();
    cp_wait<0>();
    __syncthreads();

    // loop-invariant bias fragments
    float2 bqr[4], bkr[4], bvr[4];
    #pragma unroll
    for (int ni = 0; ni < 4; ++ni) {
        int col = wn * 32 + ni * 8 + tg * 2;
        bqr[ni] = make_float2(__ldg(bq + col), __ldg(bq + col + 1));
        bkr[ni] = make_float2(__ldg(bk + col), __ldg(bk + col + 1));
        bvr[ni] = make_float2(__ldg(bv + col), __ldg(bv + col + 1));
    }

    for (int t = blockIdx.x; t < NTILES; t += PGRID) {
        size_t e0 = (size_t)t * 64;

        // prefetch this tile's edge indices (hidden under the GEMM)
        int srcR[2][2], dstR[2][2];
        #pragma unroll
        for (int mi = 0; mi < 2; ++mi)
            #pragma unroll
            for (int sr = 0; sr < 2; ++sr) {
                int row = wm * 32 + mi * 16 + sr * 8 + gr;
                srcR[mi][sr] = node_of(idx, is64, e0 + row);
                dstR[mi][sr] = node_of(idx, is64, (size_t)E_EDGES + e0 + row);
            }

        // triple GEMM: acc[0]=Q, acc[1]=K, acc[2]=V
        float acc[3][2][4][4];
        gemm_multi<3>(As, Wq_, Wk_, Wv_, acc, wm, wn, gr, tg);

        // scores for head wn: (Q+bq).(K+bk), quad shuffle, exp
        float ev[4];
        #pragma unroll
        for (int mi = 0; mi < 2; ++mi) {
            float s0 = 0.f, s1 = 0.f;
            #pragma unroll
            for (int ni = 0; ni < 4; ++ni) {
                s0 += (acc[0][mi][ni][0] + bqr[ni].x) * (acc[1][mi][ni][0] + bkr[ni].x)
                    + (acc[0][mi][ni][1] + bqr[ni].y) * (acc[1][mi][ni][1] + bkr[ni].y);
                s1 += (acc[0][mi][ni][2] + bqr[ni].x) * (acc[1][mi][ni][2] + bkr[ni].x)
                    + (acc[0][mi][ni][3] + bqr[ni].y) * (acc[1][mi][ni][3] + bkr[ni].y);
            }
            s0 += __shfl_xor_sync(0xffffffffu, s0, 1);
            s0 += __shfl_xor_sync(0xffffffffu, s0, 2);
            s1 += __shfl_xor_sync(0xffffffffu, s1, 1);
            s1 += __shfl_xor_sync(0xffffffffu, s1, 2);
            ev[mi * 2]     = __expf(s0 * SCALEF);
            ev[mi * 2 + 1] = __expf(s1 * SCALEF);
        }

        __syncthreads();   // all warps done reading As

        // stream next A tile straight into smem (no registers, no STS pass)
        int tn = t + PGRID;
        if (tn < NTILES) {
            size_t en = (size_t)tn * 64;
            for (int i = tid; i < 2048; i += 256) {
                int r = i >> 5, c = (i & 31) << 2;
                cp_async16(As + r * 128 + (c ^ ((r & 7) << 2)),
                           X + (en + r) * DMODEL + c);
            }
            cp_commit();
        }

        // scatter: weighted V to src & dst, den per head (REDG: fire-and-forget)
        #pragma unroll
        for (int mi = 0; mi < 2; ++mi) {
            #pragma unroll
            for (int sr = 0; sr < 2; ++sr) {
                int src = srcR[mi][sr], dst = dstR[mi][sr];
                float* ps = g_S + (size_t)src * DMODEL;
                float* pd = g_S + (size_t)dst * DMODEL;
                float w = ev[mi * 2 + sr];
                if (tg == 0) {
                    red_add_f(&g_den[(size_t)src * 4 + wn], w);
                    red_add_f(&g_den[(size_t)dst * 4 + wn], w);
                }
                #pragma unroll
                for (int ni = 0; ni < 4; ++ni) {
                    int col = wn * 32 + ni * 8 + tg * 2;
                    float v0 = (acc[2][mi][ni][sr * 2]     + bvr[ni].x) * w;
                    float v1 = (acc[2][mi][ni][sr * 2 + 1] + bvr[ni].y) * w;
                    float p0 = __shfl_xor_sync(0xffffffffu, v0, 1);
                    float p1 = __shfl_xor_sync(0xffffffffu, v1, 1);
                    if (!(tg & 1)) {
                        red_add_v4(ps + col, v0, v1, p0, p1);
                        red_add_v4(pd + col, v0, v1, p0, p1);
                    }
                }
            }
        }

        cp_wait<0>();
        __syncthreads();   // next As ready
    }
}

// ---------------- kernel 4: per-NODE Wo GEMM: T = (0.5*S/den) @ Wo -----------
// 64-row node tiles, 96KB smem -> 2 CTAs/SM.
__global__ __launch_bounds__(256, 2)
void nodeT_kernel() {
    extern __shared__ float sm[];
    float* Ms = sm;                  // [64][128] swizzled node msg tile
    float* Wo_ = sm + 64 * 128;      // [128][128] paired-k Wo

    int tid = threadIdx.x, lane = tid & 31, warp = tid >> 5;
    int wm = warp & 1, wn = warp >> 1, gr = lane >> 2, tg = lane & 3;
    size_t n0 = (size_t)blockIdx.x * 64;

    for (int i = tid; i < 4096; i += 256)
        cp_async16(Wo_ + i * 4, ((const float*)g_Wt[3]) + i * 4);
    cp_commit();

    {   // build tile: 4 threads per row, one head (32 cols) each
        int r = tid >> 2, hd = tid & 3;
        size_t node = n0 + r;
        float d = g_den[node * 4 + hd];
        float f = (d > 0.f) ? 0.5f / d : 0.f;
        const float* Sp = g_S + node * DMODEL + hd * 32;
        int s = (r & 7) << 2;
        #pragma unroll
        for (int j = 0; j < 8; ++j) {
            int c = hd * 32 + j * 4;
            float4 a = *(const float4*)(Sp + j * 4);
            *(float4*)(Ms + r * 128 + (c ^ s)) =
                make_float4(a.x * f, a.y * f, a.z * f, a.w * f);
        }
    }
    cp_wait<0>();
    __syncthreads();

    float acc[1][2][4][4];
    gemm_multi<1>(Ms, Wo_, Wo_, Wo_, acc, wm, wn, gr, tg);

    #pragma unroll
    for (int mi = 0; mi < 2; ++mi) {
        int r0 = wm * 32 + mi * 16 + gr;
        #pragma unroll
        for (int ni = 0; ni < 4; ++ni) {
            int col = wn * 32 + ni * 8 + tg * 2;
            *(float2*)(g_T + (n0 + r0) * DMODEL + col)     = make_float2(acc[0][mi][ni][0], acc[0][mi][ni][1]);
            *(float2*)(g_T + (n0 + r0 + 8) * DMODEL + col) = make_float2(acc[0][mi][ni][2], acc[0][mi][ni][3]);
        }
    }
}

// ---------------- kernel 5: edge epilogue: LN(T[src]+T[dst]+bo+X) ------------
__global__ __launch_bounds__(256)
void epi_kernel(const void* __restrict__ idx, const float* __restrict__ X,
                const float* __restrict__ bo, const float* __restrict__ gamma,
                const float* __restrict__ beta, float* __restrict__ out) {
    int tid = threadIdx.x, lane = tid & 31;
    size_t e = (size_t)blockIdx.x * 8 + (tid >> 5);
    int is64 = g_is64;

    int src = node_of(idx, is64, e);
    int dst = node_of(idx, is64, (size_t)E_EDGES + e);

    int c = lane * 4;
    float4 ts = *(const float4*)(g_T + (size_t)src * DMODEL + c);
    float4 td = *(const float4*)(g_T + (size_t)dst * DMODEL + c);
    float4 x4 = *(const float4*)(X + e * DMODEL + c);
    float4 b4 = *(const float4*)(bo + c);

    float4 v;
    v.x = ts.x + td.x + b4.x + x4.x;
    v.y = ts.y + td.y + b4.y + x4.y;
    v.z = ts.z + td.z + b4.z + x4.z;
    v.w = ts.w + td.w + b4.w + x4.w;

    float s = v.x + v.y + v.z + v.w;
    float q = v.x * v.x + v.y * v.y + v.z * v.z + v.w * v.w;
    #pragma unroll
    for (int o = 16; o > 0; o >>= 1) {
        s += __shfl_xor_sync(0xffffffffu, s, o);
        q += __shfl_xor_sync(0xffffffffu, q, o);
    }
    float mu = s * (1.0f / 128.0f);
    float var = q * (1.0f / 128.0f) - mu * mu;
    float rstd = rsqrtf(var + LN_EPSF);

    float4 g4 = *(const float4*)(gamma + c);
    float4 be = *(const float4*)(beta + c);
    float4 o4;
    o4.x = (v.x - mu) * rstd * g4.x + be.x;
    o4.y = (v.y - mu) * rstd * g4.y + be.y;
    o4.z = (v.z - mu) * rstd * g4.z + be.z;
    o4.w = (v.w - mu) * rstd * g4.w + be.w;
    *(float4*)(out + e * DMODEL + c) = o4;
}

// ---------------- host -------------------------------------------------------
#define SMEM_P     ((64 * 128 + 3 * 128 * 128) * 4)
#define SMEM_NODE  ((64 * 128 + 128 * 128) * 4)

extern "C" void kernel_launch(void* const* d_in, const int* in_sizes, int n_in,
                              void* d_out, int out_size) {
    const float* X   = (const float*)d_in[0];
    const void*  idx = d_in[1];
    int base = 2;
    if (n_in >= 13 && in_sizes[2] == 1) base = 3;
    const float* Wq    = (const float*)d_in[base + 0];
    const float* bq    = (const float*)d_in[base + 1];
    const float* Wk    = (const float*)d_in[base + 2];
    const float* bk    = (const float*)d_in[base + 3];
    const float* Wv    = (const float*)d_in[base + 4];
    const float* bv    = (const float*)d_in[base + 5];
    const float* Wo    = (const float*)d_in[base + 6];
    const float* bo    = (const float*)d_in[base + 7];
    const float* gamma = (const float*)d_in[base + 8];
    const float* beta  = (const float*)d_in[base + 9];
    float* out = (float*)d_out;

    cudaFuncSetAttribute(fusedP_kernel, cudaFuncAttributeMaxDynamicSharedMemorySize, SMEM_P);
    cudaFuncSetAttribute(nodeT_kernel,  cudaFuncAttributeMaxDynamicSharedMemorySize, SMEM_NODE);

    detect_kernel<<<1, 32>>>((const int*)idx);
    init_kernel<<<8192, 256>>>();
    prep_kernel<<<dim3(4, 4, 4), dim3(32, 8)>>>(Wq, Wk, Wv, Wo);
    fusedP_kernel<<<PGRID, 256, SMEM_P>>>(X, idx, bq, bk, bv);
    nodeT_kernel<<<NNODES / 64, 256, SMEM_NODE>>>();
    epi_kernel<<<E_EDGES / 8, 256>>>(idx, X, bo, gamma, beta, out);
}